// round 4
// baseline (speedup 1.0000x reference)
#include <cuda_runtime.h>
#include <math.h>

#define BB 4096
#define LL 32
#define DD 300
#define HH 6
#define HDD 50
#define KP 304          // padded K (38 chunks of 8)
#define NP 320          // padded N per matrix (40 chunks of 8)
#define NKC 38
#define XS 324          // smem row stride (floats): gid*4+ctg -> perfect 32-bank permutation
#define MT 128          // rows per GEMM CTA
#define GT 512          // threads in GEMM CTAs (16 warps: 2 in M x 8 in N)
#define AS 308          // attention smem stride

// tf32-rounded zero-padded weights: g_Wr[m][n*KP+k], m: Wq,Wk,Wv,Wo,Va
__device__ float g_Wr[5][NP * KP];
__device__ float g_qkv[3][(size_t)BB * LL * KP];
__device__ float g_ctx[(size_t)BB * LL * KP];

__device__ __forceinline__ float tf32r(float x) {
    unsigned r;
    asm("cvt.rna.tf32.f32 %0, %1;" : "=r"(r) : "f"(x));
    return __uint_as_float(r);
}

__device__ __forceinline__ void mma8(float c[4], const float a[4], float b0, float b1) {
    asm volatile(
        "mma.sync.aligned.m16n8k8.row.col.f32.tf32.tf32.f32 "
        "{%0,%1,%2,%3},{%4,%5,%6,%7},{%8,%9},{%0,%1,%2,%3};"
        : "+f"(c[0]), "+f"(c[1]), "+f"(c[2]), "+f"(c[3])
        : "r"(__float_as_uint(a[0])), "r"(__float_as_uint(a[1])),
          "r"(__float_as_uint(a[2])), "r"(__float_as_uint(a[3])),
          "r"(__float_as_uint(b0)), "r"(__float_as_uint(b1)));
}

__global__ void prep_kernel(const float* __restrict__ Wq, const float* __restrict__ Wk,
                            const float* __restrict__ Wv, const float* __restrict__ Wo,
                            const float* __restrict__ Va) {
    const float* src;
    int m = blockIdx.y;
    switch (m) {
        case 0: src = Wq; break;
        case 1: src = Wk; break;
        case 2: src = Wv; break;
        case 3: src = Wo; break;
        default: src = Va; break;
    }
    float* dst = g_Wr[m];
    for (int idx = blockIdx.x * blockDim.x + threadIdx.x; idx < NP * KP;
         idx += gridDim.x * blockDim.x) {
        int n = idx / KP, k = idx - n * KP;
        dst[idx] = (n < DD && k < DD) ? tf32r(src[n * DD + k]) : 0.f;
    }
}

// ---------------- Kernel A: fused gather + one of {Q,K,V} GEMM ----------------
__global__ __launch_bounds__(GT, 1)
void qkv_kernel(const int* __restrict__ title,
                const float* __restrict__ emb,
                const float* __restrict__ pos,
                const float* __restrict__ bq,
                const float* __restrict__ bk,
                const float* __restrict__ bv) {
    extern __shared__ float Xs[];            // [MT][XS]
    __shared__ int toks[MT];

    const int tid = threadIdx.x;
    const int lane = tid & 31, wid = tid >> 5;
    const int gid = lane >> 2, ctg = lane & 3;
    const int wm = wid >> 3, wn = wid & 7;
    const int r0 = blockIdx.x * MT;
    const int g  = blockIdx.y;

    if (tid < MT) toks[tid] = title[r0 + tid];
    __syncthreads();

    // gather x = tf32(emb[token] + pos), zero-pad cols >= 300
    for (int idx = tid; idx < MT * 81; idx += GT) {
        int r = idx / 81, j = idx - r * 81;
        float4 v = make_float4(0.f, 0.f, 0.f, 0.f);
        if (j < 75) {
            float4 e = *(const float4*)&emb[(size_t)toks[r] * DD + 4 * j];
            float4 p = *(const float4*)&pos[(r & (LL - 1)) * DD + 4 * j];
            v.x = tf32r(e.x + p.x); v.y = tf32r(e.y + p.y);
            v.z = tf32r(e.z + p.z); v.w = tf32r(e.w + p.w);
        }
        *(float4*)&Xs[r * XS + 4 * j] = v;
    }
    __syncthreads();

    const float* Wg = g_Wr[g];
    float c[4][5][4];
    #pragma unroll
    for (int mf = 0; mf < 4; ++mf)
        #pragma unroll
        for (int nc = 0; nc < 5; ++nc)
            #pragma unroll
            for (int i = 0; i < 4; ++i) c[mf][nc][i] = 0.f;

    for (int kc = 0; kc < NKC; ++kc) {
        const int k0 = kc * 8;
        float a[4][4];
        #pragma unroll
        for (int mf = 0; mf < 4; ++mf) {
            const float* xr = Xs + (wm * 64 + mf * 16 + gid) * XS + k0;
            a[mf][0] = xr[ctg];
            a[mf][1] = xr[8 * XS + ctg];
            a[mf][2] = xr[ctg + 4];
            a[mf][3] = xr[8 * XS + ctg + 4];
        }
        #pragma unroll
        for (int nc = 0; nc < 5; ++nc) {
            const float* wr = Wg + (wn * 40 + nc * 8 + gid) * KP + k0;
            float b0 = wr[ctg], b1 = wr[ctg + 4];
            #pragma unroll
            for (int mf = 0; mf < 4; ++mf) mma8(c[mf][nc], a[mf], b0, b1);
        }
    }

    const float* bias = (g == 0) ? bq : (g == 1) ? bk : bv;
    const float scale = (g == 0) ? rsqrtf((float)HDD) : 1.f;

    __syncthreads();                              // done reading Xs
    #pragma unroll
    for (int mf = 0; mf < 4; ++mf)
        #pragma unroll
        for (int nc = 0; nc < 5; ++nc)
            #pragma unroll
            for (int i = 0; i < 4; ++i) {
                int n = wn * 40 + nc * 8 + 2 * ctg + (i & 1);
                int r = wm * 64 + mf * 16 + gid + (i >> 1) * 8;
                float v = 0.f;
                if (n < DD) v = (c[mf][nc][i] + bias[n]) * scale;
                Xs[r * XS + n] = v;
            }
    __syncthreads();

    float* dst = g_qkv[g];
    for (int idx = tid; idx < MT * 76; idx += GT) {
        int r = idx / 76, j = idx - r * 76;
        *(float4*)&dst[(size_t)(r0 + r) * KP + 4 * j] = *(float4*)&Xs[r * XS + 4 * j];
    }
}

// ---------------- Kernel C: attention per batch row ----------------
__global__ __launch_bounds__(192, 1)
void attn_kernel(float* __restrict__ dummy) {
    extern __shared__ float sm[];
    float* SQ = sm;
    float* SK = sm + LL * AS;
    float* SV = sm + 2 * LL * AS;

    const int b = blockIdx.x;
    const int tid = threadIdx.x;

    for (int idx = tid; idx < 3 * LL * 76; idx += 192) {
        int gg = idx / (LL * 76);
        int rem = idx - gg * LL * 76;
        int r = rem / 76, j = rem - r * 76;
        float4 v = *(const float4*)&g_qkv[gg][(size_t)(b * LL + r) * KP + 4 * j];
        *(float4*)&sm[gg * LL * AS + r * AS + 4 * j] = v;
    }
    __syncthreads();

    {
        const int h = tid >> 5;            // warp == head
        const int i = tid & 31;            // lane == query row
        const int off = h * HDD;
        float s[LL];
        #pragma unroll
        for (int j = 0; j < LL; ++j) s[j] = 0.f;
        for (int hd = 0; hd < HDD; ++hd) {
            float qv = SQ[i * AS + off + hd];
            #pragma unroll
            for (int j = 0; j < LL; ++j)
                s[j] = fmaf(qv, SK[j * AS + off + hd], s[j]);
        }
        float m = -1e30f;
        #pragma unroll
        for (int j = 0; j < LL; ++j) m = fmaxf(m, s[j]);
        float sum = 0.f;
        #pragma unroll
        for (int j = 0; j < LL; ++j) { s[j] = __expf(s[j] - m); sum += s[j]; }
        float inv = 1.f / sum;
        #pragma unroll
        for (int j = 0; j < LL; ++j) s[j] *= inv;
        for (int hd = 0; hd < HDD; ++hd) {
            float cx = 0.f;
            #pragma unroll
            for (int j = 0; j < LL; ++j)
                cx = fmaf(s[j], SV[j * AS + off + hd], cx);
            SQ[i * AS + off + hd] = cx;    // overwrite own head's q cols
        }
    }
    __syncthreads();

    for (int idx = tid; idx < LL * 76; idx += 192) {
        int r = idx / 76, j = idx - r * 76;
        float4 v = *(const float4*)&SQ[r * AS + 4 * j];
        if (j == 75) v = make_float4(0.f, 0.f, 0.f, 0.f);
        else { v.x = tf32r(v.x); v.y = tf32r(v.y); v.z = tf32r(v.z); v.w = tf32r(v.w); }
        *(float4*)&g_ctx[(size_t)(b * LL + r) * KP + 4 * j] = v;
    }
}

// ---------------- Kernel DE: Wo-GEMM -> (smem ctx2) -> Va+tanh+qw -> softmax -> pool ----------------
__global__ __launch_bounds__(GT, 1)
void de_kernel(const float* __restrict__ bo,
               const float* __restrict__ ba,
               const float* __restrict__ qw,
               float* __restrict__ out) {
    extern __shared__ float Xs[];               // [MT][XS] + SP[8][128] + SA[128] + SAL[128]
    float* SP  = Xs + MT * XS;
    float* SA  = SP + 8 * MT;
    float* SAL = SA + MT;

    const int tid = threadIdx.x;
    const int lane = tid & 31, wid = tid >> 5;
    const int gid = lane >> 2, ctg = lane & 3;
    const int wm = wid >> 3, wn = wid & 7;
    const int r0 = blockIdx.x * MT;

    // stage ctx
    for (int idx = tid; idx < MT * 76; idx += GT) {
        int r = idx / 76, j = idx - r * 76;
        *(float4*)&Xs[r * XS + 4 * j] = *(const float4*)&g_ctx[(size_t)(r0 + r) * KP + 4 * j];
    }
    __syncthreads();

    // ---- D: ctx2 = ctx @ Wo^T + bo ----
    {
        const float* Wg = g_Wr[3];
        float c[4][5][4];
        #pragma unroll
        for (int mf = 0; mf < 4; ++mf)
            #pragma unroll
            for (int nc = 0; nc < 5; ++nc)
                #pragma unroll
                for (int i = 0; i < 4; ++i) c[mf][nc][i] = 0.f;
        for (int kc = 0; kc < NKC; ++kc) {
            const int k0 = kc * 8;
            float a[4][4];
            #pragma unroll
            for (int mf = 0; mf < 4; ++mf) {
                const float* xr = Xs + (wm * 64 + mf * 16 + gid) * XS + k0;
                a[mf][0] = xr[ctg];
                a[mf][1] = xr[8 * XS + ctg];
                a[mf][2] = xr[ctg + 4];
                a[mf][3] = xr[8 * XS + ctg + 4];
            }
            #pragma unroll
            for (int nc = 0; nc < 5; ++nc) {
                const float* wr = Wg + (wn * 40 + nc * 8 + gid) * KP + k0;
                float b0 = wr[ctg], b1 = wr[ctg + 4];
                #pragma unroll
                for (int mf = 0; mf < 4; ++mf) mma8(c[mf][nc], a[mf], b0, b1);
            }
        }
        __syncthreads();
        #pragma unroll
        for (int mf = 0; mf < 4; ++mf)
            #pragma unroll
            for (int nc = 0; nc < 5; ++nc)
                #pragma unroll
                for (int i = 0; i < 4; ++i) {
                    int n = wn * 40 + nc * 8 + 2 * ctg + (i & 1);
                    int r = wm * 64 + mf * 16 + gid + (i >> 1) * 8;
                    float v = 0.f;
                    if (n < DD) v = c[mf][nc][i] + bo[n];
                    Xs[r * XS + n] = v;          // ctx2 stays in smem, full fp32
                }
    }
    __syncthreads();

    // ---- E: scores a[l] = sum_n tanh(ctx2@Va^T + ba)[l][n] * qw[n] ----
    {
        const float* Wg = g_Wr[4];
        float c[4][5][4];
        #pragma unroll
        for (int mf = 0; mf < 4; ++mf)
            #pragma unroll
            for (int nc = 0; nc < 5; ++nc)
                #pragma unroll
                for (int i = 0; i < 4; ++i) c[mf][nc][i] = 0.f;
        for (int kc = 0; kc < NKC; ++kc) {
            const int k0 = kc * 8;
            float a[4][4];
            #pragma unroll
            for (int mf = 0; mf < 4; ++mf) {
                const float* xr = Xs + (wm * 64 + mf * 16 + gid) * XS + k0;
                a[mf][0] = xr[ctg];
                a[mf][1] = xr[8 * XS + ctg];
                a[mf][2] = xr[ctg + 4];
                a[mf][3] = xr[8 * XS + ctg + 4];
            }
            #pragma unroll
            for (int nc = 0; nc < 5; ++nc) {
                const float* wr = Wg + (wn * 40 + nc * 8 + gid) * KP + k0;
                float b0 = wr[ctg], b1 = wr[ctg + 4];
                #pragma unroll
                for (int mf = 0; mf < 4; ++mf) mma8(c[mf][nc], a[mf], b0, b1);
            }
        }
        // per-thread row partials (rows: wm*64 + mf*16 + gid + h*8)
        float p[4][2];
        #pragma unroll
        for (int mf = 0; mf < 4; ++mf) { p[mf][0] = 0.f; p[mf][1] = 0.f; }
        #pragma unroll
        for (int mf = 0; mf < 4; ++mf)
            #pragma unroll
            for (int nc = 0; nc < 5; ++nc)
                #pragma unroll
                for (int i = 0; i < 4; ++i) {
                    int n = wn * 40 + nc * 8 + 2 * ctg + (i & 1);
                    if (n < DD) {
                        float tv = tanhf(c[mf][nc][i] + ba[n]);
                        p[mf][i >> 1] = fmaf(tv, qw[n], p[mf][i >> 1]);
                    }
                }
        // reduce over ctg (lanes gid*4 + {0..3})
        #pragma unroll
        for (int mf = 0; mf < 4; ++mf)
            #pragma unroll
            for (int h = 0; h < 2; ++h) {
                float v = p[mf][h];
                v += __shfl_xor_sync(0xffffffffu, v, 1);
                v += __shfl_xor_sync(0xffffffffu, v, 2);
                p[mf][h] = v;
            }
        if (ctg == 0) {
            #pragma unroll
            for (int mf = 0; mf < 4; ++mf)
                #pragma unroll
                for (int h = 0; h < 2; ++h) {
                    int r = wm * 64 + mf * 16 + gid + h * 8;
                    SP[wn * MT + r] = p[mf][h];
                }
        }
    }
    __syncthreads();
    if (tid < MT) {
        float s = 0.f;
        #pragma unroll
        for (int w = 0; w < 8; ++w) s += SP[w * MT + tid];
        SA[tid] = s;
    }
    __syncthreads();

    // softmax over L per batch row (4 rows per CTA, warp each)
    if (wid < 4) {
        float v = SA[wid * LL + lane];
        float m = v;
        #pragma unroll
        for (int o = 16; o; o >>= 1) m = fmaxf(m, __shfl_xor_sync(0xffffffffu, m, o));
        float e = __expf(v - m);
        float sum = e;
        #pragma unroll
        for (int o = 16; o; o >>= 1) sum += __shfl_xor_sync(0xffffffffu, sum, o);
        SAL[wid * LL + lane] = e / sum;
    }
    __syncthreads();

    // out[b][d] = sum_l alpha * ctx2[l][d]
    for (int idx = tid; idx < 4 * DD; idx += GT) {
        int bb = idx / DD, d = idx - bb * DD;
        float o = 0.f;
        #pragma unroll
        for (int l = 0; l < LL; ++l)
            o = fmaf(SAL[bb * LL + l], Xs[(bb * LL + l) * XS + d], o);
        out[(size_t)(blockIdx.x * 4 + bb) * DD + d] = o;
    }
}

extern "C" void kernel_launch(void* const* d_in, const int* in_sizes, int n_in,
                              void* d_out, int out_size) {
    const int*   title = (const int*)  d_in[0];
    const float* emb   = (const float*)d_in[1];
    const float* pos   = (const float*)d_in[2];
    const float* Wq    = (const float*)d_in[3];
    const float* bq    = (const float*)d_in[4];
    const float* Wk    = (const float*)d_in[5];
    const float* bk    = (const float*)d_in[6];
    const float* Wv    = (const float*)d_in[7];
    const float* bv    = (const float*)d_in[8];
    const float* Wo    = (const float*)d_in[9];
    const float* bo    = (const float*)d_in[10];
    const float* Va    = (const float*)d_in[11];
    const float* ba    = (const float*)d_in[12];
    const float* qw    = (const float*)d_in[13];
    float* out = (float*)d_out;

    size_t sh_gemm = (size_t)MT * XS * sizeof(float);                       // 165,888
    size_t sh_de   = sh_gemm + (size_t)(8 * MT + 2 * MT) * sizeof(float);   // +5,120
    size_t sh_attn = (size_t)3 * LL * AS * sizeof(float);                   // 118,272

    cudaFuncSetAttribute(qkv_kernel, cudaFuncAttributeMaxDynamicSharedMemorySize, (int)sh_gemm);
    cudaFuncSetAttribute(de_kernel,  cudaFuncAttributeMaxDynamicSharedMemorySize, (int)sh_de);
    cudaFuncSetAttribute(attn_kernel,cudaFuncAttributeMaxDynamicSharedMemorySize, (int)sh_attn);

    dim3 pgrid(48, 5);
    prep_kernel<<<pgrid, 256>>>(Wq, Wk, Wv, Wo, Va);

    dim3 agrid(BB * LL / MT, 3);       // 1024 x 3
    qkv_kernel<<<agrid, GT, sh_gemm>>>(title, emb, pos, bq, bk, bv);

    attn_kernel<<<BB, 192, sh_attn>>>(nullptr);

    de_kernel<<<BB * LL / MT, GT, sh_de>>>(bo, ba, qw, out);
}

// round 5
// speedup vs baseline: 1.7103x; 1.7103x over previous
#include <cuda_runtime.h>
#include <math.h>

#define BB 4096
#define LL 32
#define DD 300
#define HH 6
#define HDD 50
#define KP 304          // padded K (38 chunks of 8); also row stride of intermediates
#define NKC 38
#define XS 324          // smem row stride (floats) -> conflict-free A-frag LDS
#define MT 128          // rows per GEMM CTA
#define GT 512          // 16 warps: 2 in M x 8 in N (warp tile 64 x 40)
#define AS 308          // attention smem stride

// Fragment-packed weights: g_Wb[m][((kc*8 + wn)*5 + nc)*32 + lane] =
//   { W[wn*40+nc*8+gid][kc*8+ctg], W[...][kc*8+ctg+4] }   (zero-padded, tf32-rounded)
#define WB_PER_M (NKC * 8 * 5 * 32)     // 48640 float2 per matrix
__device__ float2 g_Wb[5][WB_PER_M];
__device__ float g_qkv[3][(size_t)BB * LL * KP];
__device__ float g_ctx[(size_t)BB * LL * KP];

__device__ __forceinline__ float tf32r(float x) {
    unsigned r;
    asm("cvt.rna.tf32.f32 %0, %1;" : "=r"(r) : "f"(x));
    return __uint_as_float(r);
}

__device__ __forceinline__ void mma8(float c[4], const float a[4], float b0, float b1) {
    asm volatile(
        "mma.sync.aligned.m16n8k8.row.col.f32.tf32.tf32.f32 "
        "{%0,%1,%2,%3},{%4,%5,%6,%7},{%8,%9},{%0,%1,%2,%3};"
        : "+f"(c[0]), "+f"(c[1]), "+f"(c[2]), "+f"(c[3])
        : "r"(__float_as_uint(a[0])), "r"(__float_as_uint(a[1])),
          "r"(__float_as_uint(a[2])), "r"(__float_as_uint(a[3])),
          "r"(__float_as_uint(b0)), "r"(__float_as_uint(b1)));
}

__global__ void prep_kernel(const float* __restrict__ Wq, const float* __restrict__ Wk,
                            const float* __restrict__ Wv, const float* __restrict__ Wo,
                            const float* __restrict__ Va) {
    const float* src;
    int m = blockIdx.y;
    switch (m) {
        case 0: src = Wq; break;
        case 1: src = Wk; break;
        case 2: src = Wv; break;
        case 3: src = Wo; break;
        default: src = Va; break;
    }
    float2* dst = g_Wb[m];
    for (int idx = blockIdx.x * blockDim.x + threadIdx.x; idx < WB_PER_M;
         idx += gridDim.x * blockDim.x) {
        int lane = idx & 31;
        int t1   = idx >> 5;         // (kc*8 + wn)*5 + nc
        int nc   = t1 % 5;
        int t2   = t1 / 5;           // kc*8 + wn
        int wn   = t2 & 7;
        int kc   = t2 >> 3;
        int gid = lane >> 2, ctg = lane & 3;
        int n = wn * 40 + nc * 8 + gid;
        int k = kc * 8 + ctg;
        float2 f = make_float2(0.f, 0.f);
        if (n < DD) {
            if (k < DD)     f.x = tf32r(src[n * DD + k]);
            if (k + 4 < DD) f.y = tf32r(src[n * DD + k + 4]);
        }
        dst[idx] = f;
    }
}

// ---------------- Kernel A: gather x once, then Q, K, V GEMMs ----------------
__global__ __launch_bounds__(GT)
void qkv_kernel(const int* __restrict__ title,
                const float* __restrict__ emb,
                const float* __restrict__ pos,
                const float* __restrict__ bq,
                const float* __restrict__ bk,
                const float* __restrict__ bv) {
    extern __shared__ float Xs[];            // [MT][XS]
    __shared__ int toks[MT];

    const int tid = threadIdx.x;
    const int lane = tid & 31, wid = tid >> 5;
    const int gid = lane >> 2, ctg = lane & 3;
    const int wm = wid >> 3, wn = wid & 7;
    const int r0 = blockIdx.x * MT;

    if (tid < MT) toks[tid] = title[r0 + tid];
    __syncthreads();

    // gather x = tf32(emb[token] + pos), zero-pad cols >= 300
    for (int idx = tid; idx < MT * 81; idx += GT) {
        int r = idx / 81, j = idx - r * 81;
        float4 v = make_float4(0.f, 0.f, 0.f, 0.f);
        if (j < 75) {
            float4 e = *(const float4*)&emb[(size_t)toks[r] * DD + 4 * j];
            float4 p = *(const float4*)&pos[(r & (LL - 1)) * DD + 4 * j];
            v.x = tf32r(e.x + p.x); v.y = tf32r(e.y + p.y);
            v.z = tf32r(e.z + p.z); v.w = tf32r(e.w + p.w);
        }
        *(float4*)&Xs[r * XS + 4 * j] = v;
    }
    __syncthreads();

    const float rs = rsqrtf((float)HDD);

    for (int g = 0; g < 3; ++g) {
        float c[4][5][4];
        #pragma unroll
        for (int mf = 0; mf < 4; ++mf)
            #pragma unroll
            for (int nc = 0; nc < 5; ++nc)
                #pragma unroll
                for (int i = 0; i < 4; ++i) c[mf][nc][i] = 0.f;

        const float2* wb0 = g_Wb[g] + (size_t)wn * 5 * 32 + lane;
        #pragma unroll 2
        for (int kc = 0; kc < NKC; ++kc) {
            const int k0 = kc * 8;
            float a[4][4];
            #pragma unroll
            for (int mf = 0; mf < 4; ++mf) {
                const float* xr = Xs + (wm * 64 + mf * 16 + gid) * XS + k0;
                a[mf][0] = xr[ctg];
                a[mf][1] = xr[8 * XS + ctg];
                a[mf][2] = xr[ctg + 4];
                a[mf][3] = xr[8 * XS + ctg + 4];
            }
            const float2* wb = wb0 + (size_t)kc * (8 * 5 * 32);
            #pragma unroll
            for (int nc = 0; nc < 5; ++nc) {
                float2 b = wb[nc * 32];
                #pragma unroll
                for (int mf = 0; mf < 4; ++mf) mma8(c[mf][nc], a[mf], b.x, b.y);
            }
        }

        const float* bias = (g == 0) ? bq : (g == 1) ? bk : bv;
        const float scale = (g == 0) ? rs : 1.f;
        float* dst = g_qkv[g];
        #pragma unroll
        for (int mf = 0; mf < 4; ++mf)
            #pragma unroll
            for (int nc = 0; nc < 5; ++nc) {
                int n = wn * 40 + nc * 8 + 2 * ctg;
                if (n < DD) {
                    float b0 = bias[n], b1 = bias[n + 1];
                    #pragma unroll
                    for (int h = 0; h < 2; ++h) {
                        int r = wm * 64 + mf * 16 + gid + h * 8;
                        float2 v;
                        v.x = (c[mf][nc][2 * h]     + b0) * scale;
                        v.y = (c[mf][nc][2 * h + 1] + b1) * scale;
                        *(float2*)&dst[(size_t)(r0 + r) * KP + n] = v;
                    }
                }
            }
    }
}

// ---------------- Kernel C: attention per batch row ----------------
__global__ __launch_bounds__(192, 1)
void attn_kernel(float* __restrict__ dummy) {
    extern __shared__ float sm[];
    float* SQ = sm;
    float* SK = sm + LL * AS;
    float* SV = sm + 2 * LL * AS;

    const int b = blockIdx.x;
    const int tid = threadIdx.x;

    for (int idx = tid; idx < 3 * LL * 76; idx += 192) {
        int gg = idx / (LL * 76);
        int rem = idx - gg * LL * 76;
        int r = rem / 76, j = rem - r * 76;
        float4 v = *(const float4*)&g_qkv[gg][(size_t)(b * LL + r) * KP + 4 * j];
        *(float4*)&sm[gg * LL * AS + r * AS + 4 * j] = v;
    }
    __syncthreads();

    {
        const int h = tid >> 5;            // warp == head
        const int i = tid & 31;            // lane == query row
        const int off = h * HDD;
        float s[LL];
        #pragma unroll
        for (int j = 0; j < LL; ++j) s[j] = 0.f;
        for (int hd = 0; hd < HDD; ++hd) {
            float qv = SQ[i * AS + off + hd];
            #pragma unroll
            for (int j = 0; j < LL; ++j)
                s[j] = fmaf(qv, SK[j * AS + off + hd], s[j]);
        }
        float m = -1e30f;
        #pragma unroll
        for (int j = 0; j < LL; ++j) m = fmaxf(m, s[j]);
        float sum = 0.f;
        #pragma unroll
        for (int j = 0; j < LL; ++j) { s[j] = __expf(s[j] - m); sum += s[j]; }
        float inv = 1.f / sum;
        #pragma unroll
        for (int j = 0; j < LL; ++j) s[j] *= inv;
        for (int hd = 0; hd < HDD; ++hd) {
            float cx = 0.f;
            #pragma unroll
            for (int j = 0; j < LL; ++j)
                cx = fmaf(s[j], SV[j * AS + off + hd], cx);
            SQ[i * AS + off + hd] = cx;
        }
    }
    __syncthreads();

    for (int idx = tid; idx < LL * 76; idx += 192) {
        int r = idx / 76, j = idx - r * 76;
        float4 v = *(const float4*)&SQ[r * AS + 4 * j];
        if (j == 75) v = make_float4(0.f, 0.f, 0.f, 0.f);
        else { v.x = tf32r(v.x); v.y = tf32r(v.y); v.z = tf32r(v.z); v.w = tf32r(v.w); }
        *(float4*)&g_ctx[(size_t)(b * LL + r) * KP + 4 * j] = v;
    }
}

// ---------------- Kernel DE: Wo-GEMM -> smem ctx2 -> Va+tanh+qw -> softmax -> pool ----------------
__global__ __launch_bounds__(GT)
void de_kernel(const float* __restrict__ bo,
               const float* __restrict__ ba,
               const float* __restrict__ qw,
               float* __restrict__ out) {
    extern __shared__ float Xs[];               // [MT][XS] + SP[8][128] + SA[128] + SAL[128]
    float* SP  = Xs + MT * XS;
    float* SA  = SP + 8 * MT;
    float* SAL = SA + MT;

    const int tid = threadIdx.x;
    const int lane = tid & 31, wid = tid >> 5;
    const int gid = lane >> 2, ctg = lane & 3;
    const int wm = wid >> 3, wn = wid & 7;
    const int r0 = blockIdx.x * MT;

    for (int idx = tid; idx < MT * 76; idx += GT) {
        int r = idx / 76, j = idx - r * 76;
        *(float4*)&Xs[r * XS + 4 * j] = *(const float4*)&g_ctx[(size_t)(r0 + r) * KP + 4 * j];
    }
    __syncthreads();

    // ---- D: ctx2 = ctx @ Wo^T + bo ----
    {
        float c[4][5][4];
        #pragma unroll
        for (int mf = 0; mf < 4; ++mf)
            #pragma unroll
            for (int nc = 0; nc < 5; ++nc)
                #pragma unroll
                for (int i = 0; i < 4; ++i) c[mf][nc][i] = 0.f;
        const float2* wb0 = g_Wb[3] + (size_t)wn * 5 * 32 + lane;
        #pragma unroll 2
        for (int kc = 0; kc < NKC; ++kc) {
            const int k0 = kc * 8;
            float a[4][4];
            #pragma unroll
            for (int mf = 0; mf < 4; ++mf) {
                const float* xr = Xs + (wm * 64 + mf * 16 + gid) * XS + k0;
                a[mf][0] = xr[ctg];
                a[mf][1] = xr[8 * XS + ctg];
                a[mf][2] = xr[ctg + 4];
                a[mf][3] = xr[8 * XS + ctg + 4];
            }
            const float2* wb = wb0 + (size_t)kc * (8 * 5 * 32);
            #pragma unroll
            for (int nc = 0; nc < 5; ++nc) {
                float2 b = wb[nc * 32];
                #pragma unroll
                for (int mf = 0; mf < 4; ++mf) mma8(c[mf][nc], a[mf], b.x, b.y);
            }
        }
        __syncthreads();
        #pragma unroll
        for (int mf = 0; mf < 4; ++mf)
            #pragma unroll
            for (int nc = 0; nc < 5; ++nc)
                #pragma unroll
                for (int i = 0; i < 4; ++i) {
                    int n = wn * 40 + nc * 8 + 2 * ctg + (i & 1);
                    int r = wm * 64 + mf * 16 + gid + (i >> 1) * 8;
                    float v = 0.f;
                    if (n < DD) v = c[mf][nc][i] + bo[n];
                    Xs[r * XS + n] = v;          // ctx2 stays in smem, full fp32
                }
    }
    __syncthreads();

    // ---- E: a[l] = sum_n tanh(ctx2@Va^T + ba)[l][n] * qw[n] ----
    {
        float c[4][5][4];
        #pragma unroll
        for (int mf = 0; mf < 4; ++mf)
            #pragma unroll
            for (int nc = 0; nc < 5; ++nc)
                #pragma unroll
                for (int i = 0; i < 4; ++i) c[mf][nc][i] = 0.f;
        const float2* wb0 = g_Wb[4] + (size_t)wn * 5 * 32 + lane;
        #pragma unroll 2
        for (int kc = 0; kc < NKC; ++kc) {
            const int k0 = kc * 8;
            float a[4][4];
            #pragma unroll
            for (int mf = 0; mf < 4; ++mf) {
                const float* xr = Xs + (wm * 64 + mf * 16 + gid) * XS + k0;
                a[mf][0] = xr[ctg];
                a[mf][1] = xr[8 * XS + ctg];
                a[mf][2] = xr[ctg + 4];
                a[mf][3] = xr[8 * XS + ctg + 4];
            }
            const float2* wb = wb0 + (size_t)kc * (8 * 5 * 32);
            #pragma unroll
            for (int nc = 0; nc < 5; ++nc) {
                float2 b = wb[nc * 32];
                #pragma unroll
                for (int mf = 0; mf < 4; ++mf) mma8(c[mf][nc], a[mf], b.x, b.y);
            }
        }
        float p[4][2];
        #pragma unroll
        for (int mf = 0; mf < 4; ++mf) { p[mf][0] = 0.f; p[mf][1] = 0.f; }
        #pragma unroll
        for (int mf = 0; mf < 4; ++mf)
            #pragma unroll
            for (int nc = 0; nc < 5; ++nc)
                #pragma unroll
                for (int i = 0; i < 4; ++i) {
                    int n = wn * 40 + nc * 8 + 2 * ctg + (i & 1);
                    if (n < DD) {
                        float tv = tanhf(c[mf][nc][i] + ba[n]);
                        p[mf][i >> 1] = fmaf(tv, qw[n], p[mf][i >> 1]);
                    }
                }
        #pragma unroll
        for (int mf = 0; mf < 4; ++mf)
            #pragma unroll
            for (int h = 0; h < 2; ++h) {
                float v = p[mf][h];
                v += __shfl_xor_sync(0xffffffffu, v, 1);
                v += __shfl_xor_sync(0xffffffffu, v, 2);
                p[mf][h] = v;
            }
        if (ctg == 0) {
            #pragma unroll
            for (int mf = 0; mf < 4; ++mf)
                #pragma unroll
                for (int h = 0; h < 2; ++h) {
                    int r = wm * 64 + mf * 16 + gid + h * 8;
                    SP[wn * MT + r] = p[mf][h];
                }
        }
    }
    __syncthreads();
    if (tid < MT) {
        float s = 0.f;
        #pragma unroll
        for (int w = 0; w < 8; ++w) s += SP[w * MT + tid];
        SA[tid] = s;
    }
    __syncthreads();

    if (wid < 4) {
        float v = SA[wid * LL + lane];
        float m = v;
        #pragma unroll
        for (int o = 16; o; o >>= 1) m = fmaxf(m, __shfl_xor_sync(0xffffffffu, m, o));
        float e = __expf(v - m);
        float sum = e;
        #pragma unroll
        for (int o = 16; o; o >>= 1) sum += __shfl_xor_sync(0xffffffffu, sum, o);
        SAL[wid * LL + lane] = e / sum;
    }
    __syncthreads();

    for (int idx = tid; idx < 4 * DD; idx += GT) {
        int bb = idx / DD, d = idx - bb * DD;
        float o = 0.f;
        #pragma unroll
        for (int l = 0; l < LL; ++l)
            o = fmaf(SAL[bb * LL + l], Xs[(bb * LL + l) * XS + d], o);
        out[(size_t)(blockIdx.x * 4 + bb) * DD + d] = o;
    }
}

extern "C" void kernel_launch(void* const* d_in, const int* in_sizes, int n_in,
                              void* d_out, int out_size) {
    const int*   title = (const int*)  d_in[0];
    const float* emb   = (const float*)d_in[1];
    const float* pos   = (const float*)d_in[2];
    const float* Wq    = (const float*)d_in[3];
    const float* bq    = (const float*)d_in[4];
    const float* Wk    = (const float*)d_in[5];
    const float* bk    = (const float*)d_in[6];
    const float* Wv    = (const float*)d_in[7];
    const float* bv    = (const float*)d_in[8];
    const float* Wo    = (const float*)d_in[9];
    const float* bo    = (const float*)d_in[10];
    const float* Va    = (const float*)d_in[11];
    const float* ba    = (const float*)d_in[12];
    const float* qw    = (const float*)d_in[13];
    float* out = (float*)d_out;

    size_t sh_gemm = (size_t)MT * XS * sizeof(float);
    size_t sh_de   = sh_gemm + (size_t)(8 * MT + 2 * MT) * sizeof(float);
    size_t sh_attn = (size_t)3 * LL * AS * sizeof(float);

    cudaFuncSetAttribute(qkv_kernel, cudaFuncAttributeMaxDynamicSharedMemorySize, (int)sh_gemm);
    cudaFuncSetAttribute(de_kernel,  cudaFuncAttributeMaxDynamicSharedMemorySize, (int)sh_de);
    cudaFuncSetAttribute(attn_kernel,cudaFuncAttributeMaxDynamicSharedMemorySize, (int)sh_attn);

    dim3 pgrid(48, 5);
    prep_kernel<<<pgrid, 256>>>(Wq, Wk, Wv, Wo, Va);

    qkv_kernel<<<BB * LL / MT, GT, sh_gemm>>>(title, emb, pos, bq, bk, bv);

    attn_kernel<<<BB, 192, sh_attn>>>(nullptr);

    de_kernel<<<BB * LL / MT, GT, sh_de>>>(bo, ba, qw, out);
}

// round 7
// speedup vs baseline: 1.7395x; 1.0171x over previous
#include <cuda_runtime.h>
#include <math.h>

#define BB 4096
#define LL 32
#define DD 300
#define HH 6
#define HDD 50
#define KP 304          // padded K (38 chunks of 8); row stride of intermediates
#define NKC 38
#define XS 324          // smem row stride (floats) -> conflict-free A-frag LDS
#define MT 64           // rows per GEMM CTA (2 CTAs/SM)
#define GT 256          // 8 warps, all in N; warp tile 64 x 40
#define AS 308          // attention smem stride

// Fragment-packed weights: g_Wb[m][((kc*8 + wn)*5 + nc)*32 + lane] =
//   { W[wn*40+nc*8+gid][kc*8+ctg], W[...][kc*8+ctg+4] }   (zero-padded, tf32-rounded)
#define WB_PER_M (NKC * 8 * 5 * 32)
__device__ float2 g_Wb[5][WB_PER_M];
__device__ float g_qkv[3][(size_t)BB * LL * KP];
__device__ float g_ctx[(size_t)BB * LL * KP];

__device__ __forceinline__ float tf32r(float x) {
    unsigned r;
    asm("cvt.rna.tf32.f32 %0, %1;" : "=r"(r) : "f"(x));
    return __uint_as_float(r);
}

__device__ __forceinline__ float tanh_fast(float x) {
    float y;
    asm("tanh.approx.f32 %0, %1;" : "=f"(y) : "f"(x));
    return y;
}

__device__ __forceinline__ void mma8(float c[4], const float a[4], float b0, float b1) {
    asm volatile(
        "mma.sync.aligned.m16n8k8.row.col.f32.tf32.tf32.f32 "
        "{%0,%1,%2,%3},{%4,%5,%6,%7},{%8,%9},{%0,%1,%2,%3};"
        : "+f"(c[0]), "+f"(c[1]), "+f"(c[2]), "+f"(c[3])
        : "r"(__float_as_uint(a[0])), "r"(__float_as_uint(a[1])),
          "r"(__float_as_uint(a[2])), "r"(__float_as_uint(a[3])),
          "r"(__float_as_uint(b0)), "r"(__float_as_uint(b1)));
}

__global__ void prep_kernel(const float* __restrict__ Wq, const float* __restrict__ Wk,
                            const float* __restrict__ Wv, const float* __restrict__ Wo,
                            const float* __restrict__ Va) {
    const float* src;
    int m = blockIdx.y;
    switch (m) {
        case 0: src = Wq; break;
        case 1: src = Wk; break;
        case 2: src = Wv; break;
        case 3: src = Wo; break;
        default: src = Va; break;
    }
    float2* dst = g_Wb[m];
    for (int idx = blockIdx.x * blockDim.x + threadIdx.x; idx < WB_PER_M;
         idx += gridDim.x * blockDim.x) {
        int lane = idx & 31;
        int t1   = idx >> 5;
        int nc   = t1 % 5;
        int t2   = t1 / 5;
        int wn   = t2 & 7;
        int kc   = t2 >> 3;
        int gid = lane >> 2, ctg = lane & 3;
        int n = wn * 40 + nc * 8 + gid;
        int k = kc * 8 + ctg;
        float2 f = make_float2(0.f, 0.f);
        if (n < DD) {
            if (k < DD)     f.x = tf32r(src[n * DD + k]);
            if (k + 4 < DD) f.y = tf32r(src[n * DD + k + 4]);
        }
        dst[idx] = f;
    }
}

// ---------------- Kernel A: gather x once, then Q, K, V GEMMs ----------------
__global__ __launch_bounds__(GT, 2)
void qkv_kernel(const int* __restrict__ title,
                const float* __restrict__ emb,
                const float* __restrict__ pos,
                const float* __restrict__ bq,
                const float* __restrict__ bk,
                const float* __restrict__ bv) {
    extern __shared__ float Xs[];            // [MT][XS]
    __shared__ int toks[MT];

    const int tid = threadIdx.x;
    const int lane = tid & 31, wid = tid >> 5;
    const int gid = lane >> 2, ctg = lane & 3;
    const int wn = wid;                      // 8 warps, all across N
    const int r0 = blockIdx.x * MT;

    if (tid < MT) toks[tid] = title[r0 + tid];
    __syncthreads();

    // gather x = tf32(emb[token] + pos), zero-pad cols >= 300
    for (int idx = tid; idx < MT * 81; idx += GT) {
        int r = idx / 81, j = idx - r * 81;
        float4 v = make_float4(0.f, 0.f, 0.f, 0.f);
        if (j < 75) {
            float4 e = *(const float4*)&emb[(size_t)toks[r] * DD + 4 * j];
            float4 p = *(const float4*)&pos[(r & (LL - 1)) * DD + 4 * j];
            v.x = tf32r(e.x + p.x); v.y = tf32r(e.y + p.y);
            v.z = tf32r(e.z + p.z); v.w = tf32r(e.w + p.w);
        }
        *(float4*)&Xs[r * XS + 4 * j] = v;
    }
    __syncthreads();

    const float rs = rsqrtf((float)HDD);

    for (int g = 0; g < 3; ++g) {
        float c[4][5][4];
        #pragma unroll
        for (int mf = 0; mf < 4; ++mf)
            #pragma unroll
            for (int nc = 0; nc < 5; ++nc)
                #pragma unroll
                for (int i = 0; i < 4; ++i) c[mf][nc][i] = 0.f;

        const float2* wb0 = g_Wb[g] + (size_t)wn * 5 * 32 + lane;
        #pragma unroll 2
        for (int kc = 0; kc < NKC; ++kc) {
            const int k0 = kc * 8;
            float a[4][4];
            #pragma unroll
            for (int mf = 0; mf < 4; ++mf) {
                const float* xr = Xs + (mf * 16 + gid) * XS + k0;
                a[mf][0] = xr[ctg];
                a[mf][1] = xr[8 * XS + ctg];
                a[mf][2] = xr[ctg + 4];
                a[mf][3] = xr[8 * XS + ctg + 4];
            }
            const float2* wb = wb0 + (size_t)kc * (8 * 5 * 32);
            #pragma unroll
            for (int nc = 0; nc < 5; ++nc) {
                float2 b = wb[nc * 32];
                #pragma unroll
                for (int mf = 0; mf < 4; ++mf) mma8(c[mf][nc], a[mf], b.x, b.y);
            }
        }

        const float* bias = (g == 0) ? bq : (g == 1) ? bk : bv;
        const float scale = (g == 0) ? rs : 1.f;
        float* dst = g_qkv[g];
        #pragma unroll
        for (int mf = 0; mf < 4; ++mf)
            #pragma unroll
            for (int nc = 0; nc < 5; ++nc) {
                int n = wn * 40 + nc * 8 + 2 * ctg;
                if (n < DD) {
                    float b0 = bias[n], b1 = bias[n + 1];
                    #pragma unroll
                    for (int h = 0; h < 2; ++h) {
                        int r = mf * 16 + gid + h * 8;
                        float2 v;
                        v.x = (c[mf][nc][2 * h]     + b0) * scale;
                        v.y = (c[mf][nc][2 * h + 1] + b1) * scale;
                        *(float2*)&dst[(size_t)(r0 + r) * KP + n] = v;
                    }
                }
            }
    }
}

// ---------------- Kernel C: attention per batch row ----------------
__global__ __launch_bounds__(192, 1)
void attn_kernel(float* __restrict__ dummy) {
    extern __shared__ float sm[];
    float* SQ = sm;
    float* SK = sm + LL * AS;
    float* SV = sm + 2 * LL * AS;

    const int b = blockIdx.x;
    const int tid = threadIdx.x;

    for (int idx = tid; idx < 3 * LL * 76; idx += 192) {
        int gg = idx / (LL * 76);
        int rem = idx - gg * LL * 76;
        int r = rem / 76, j = rem - r * 76;
        float4 v = *(const float4*)&g_qkv[gg][(size_t)(b * LL + r) * KP + 4 * j];
        *(float4*)&sm[gg * LL * AS + r * AS + 4 * j] = v;
    }
    __syncthreads();

    {
        const int h = tid >> 5;            // warp == head
        const int i = tid & 31;            // lane == query row
        const int off = h * HDD;
        float s[LL];
        #pragma unroll
        for (int j = 0; j < LL; ++j) s[j] = 0.f;
        for (int hd = 0; hd < HDD; ++hd) {
            float qv = SQ[i * AS + off + hd];
            #pragma unroll
            for (int j = 0; j < LL; ++j)
                s[j] = fmaf(qv, SK[j * AS + off + hd], s[j]);
        }
        float m = -1e30f;
        #pragma unroll
        for (int j = 0; j < LL; ++j) m = fmaxf(m, s[j]);
        float sum = 0.f;
        #pragma unroll
        for (int j = 0; j < LL; ++j) { s[j] = __expf(s[j] - m); sum += s[j]; }
        float inv = 1.f / sum;
        #pragma unroll
        for (int j = 0; j < LL; ++j) s[j] *= inv;
        for (int hd = 0; hd < HDD; ++hd) {
            float cx = 0.f;
            #pragma unroll
            for (int j = 0; j < LL; ++j)
                cx = fmaf(s[j], SV[j * AS + off + hd], cx);
            SQ[i * AS + off + hd] = cx;
        }
    }
    __syncthreads();

    for (int idx = tid; idx < LL * 76; idx += 192) {
        int r = idx / 76, j = idx - r * 76;
        float4 v = *(const float4*)&SQ[r * AS + 4 * j];
        if (j == 75) v = make_float4(0.f, 0.f, 0.f, 0.f);
        else { v.x = tf32r(v.x); v.y = tf32r(v.y); v.z = tf32r(v.z); v.w = tf32r(v.w); }
        *(float4*)&g_ctx[(size_t)(b * LL + r) * KP + 4 * j] = v;
    }
}

// ---------------- Kernel DE: Wo-GEMM -> smem ctx2 -> Va+tanh+qw -> softmax -> pool ----------------
__global__ __launch_bounds__(GT, 2)
void de_kernel(const float* __restrict__ bo,
               const float* __restrict__ ba,
               const float* __restrict__ qw,
               float* __restrict__ out) {
    extern __shared__ float Xs[];               // [MT][XS] + SP[8][64] + SA[64] + SAL[64]
    float* SP  = Xs + MT * XS;
    float* SA  = SP + 8 * MT;
    float* SAL = SA + MT;

    const int tid = threadIdx.x;
    const int lane = tid & 31, wid = tid >> 5;
    const int gid = lane >> 2, ctg = lane & 3;
    const int wn = wid;
    const int r0 = blockIdx.x * MT;

    for (int idx = tid; idx < MT * 76; idx += GT) {
        int r = idx / 76, j = idx - r * 76;
        *(float4*)&Xs[r * XS + 4 * j] = *(const float4*)&g_ctx[(size_t)(r0 + r) * KP + 4 * j];
    }
    __syncthreads();

    // ---- D: ctx2 = ctx @ Wo^T + bo ----
    {
        float c[4][5][4];
        #pragma unroll
        for (int mf = 0; mf < 4; ++mf)
            #pragma unroll
            for (int nc = 0; nc < 5; ++nc)
                #pragma unroll
                for (int i = 0; i < 4; ++i) c[mf][nc][i] = 0.f;
        const float2* wb0 = g_Wb[3] + (size_t)wn * 5 * 32 + lane;
        #pragma unroll 2
        for (int kc = 0; kc < NKC; ++kc) {
            const int k0 = kc * 8;
            float a[4][4];
            #pragma unroll
            for (int mf = 0; mf < 4; ++mf) {
                const float* xr = Xs + (mf * 16 + gid) * XS + k0;
                a[mf][0] = xr[ctg];
                a[mf][1] = xr[8 * XS + ctg];
                a[mf][2] = xr[ctg + 4];
                a[mf][3] = xr[8 * XS + ctg + 4];
            }
            const float2* wb = wb0 + (size_t)kc * (8 * 5 * 32);
            #pragma unroll
            for (int nc = 0; nc < 5; ++nc) {
                float2 b = wb[nc * 32];
                #pragma unroll
                for (int mf = 0; mf < 4; ++mf) mma8(c[mf][nc], a[mf], b.x, b.y);
            }
        }
        __syncthreads();
        #pragma unroll
        for (int mf = 0; mf < 4; ++mf)
            #pragma unroll
            for (int nc = 0; nc < 5; ++nc)
                #pragma unroll
                for (int i = 0; i < 4; ++i) {
                    int n = wn * 40 + nc * 8 + 2 * ctg + (i & 1);
                    int r = mf * 16 + gid + (i >> 1) * 8;
                    float v = 0.f;
                    if (n < DD) v = c[mf][nc][i] + bo[n];
                    Xs[r * XS + n] = v;          // ctx2 stays in smem, full fp32
                }
    }
    __syncthreads();

    // ---- E: a[l] = sum_n tanh(ctx2@Va^T + ba)[l][n] * qw[n] ----
    {
        float c[4][5][4];
        #pragma unroll
        for (int mf = 0; mf < 4; ++mf)
            #pragma unroll
            for (int nc = 0; nc < 5; ++nc)
                #pragma unroll
                for (int i = 0; i < 4; ++i) c[mf][nc][i] = 0.f;
        const float2* wb0 = g_Wb[4] + (size_t)wn * 5 * 32 + lane;
        #pragma unroll 2
        for (int kc = 0; kc < NKC; ++kc) {
            const int k0 = kc * 8;
            float a[4][4];
            #pragma unroll
            for (int mf = 0; mf < 4; ++mf) {
                const float* xr = Xs + (mf * 16 + gid) * XS + k0;
                a[mf][0] = xr[ctg];
                a[mf][1] = xr[8 * XS + ctg];
                a[mf][2] = xr[ctg + 4];
                a[mf][3] = xr[8 * XS + ctg + 4];
            }
            const float2* wb = wb0 + (size_t)kc * (8 * 5 * 32);
            #pragma unroll
            for (int nc = 0; nc < 5; ++nc) {
                float2 b = wb[nc * 32];
                #pragma unroll
                for (int mf = 0; mf < 4; ++mf) mma8(c[mf][nc], a[mf], b.x, b.y);
            }
        }
        float p[4][2];
        #pragma unroll
        for (int mf = 0; mf < 4; ++mf) { p[mf][0] = 0.f; p[mf][1] = 0.f; }
        #pragma unroll
        for (int mf = 0; mf < 4; ++mf)
            #pragma unroll
            for (int nc = 0; nc < 5; ++nc)
                #pragma unroll
                for (int i = 0; i < 4; ++i) {
                    int n = wn * 40 + nc * 8 + 2 * ctg + (i & 1);
                    if (n < DD) {
                        float tv = tanh_fast(c[mf][nc][i] + ba[n]);
                        p[mf][i >> 1] = fmaf(tv, qw[n], p[mf][i >> 1]);
                    }
                }
        #pragma unroll
        for (int mf = 0; mf < 4; ++mf)
            #pragma unroll
            for (int h = 0; h < 2; ++h) {
                float v = p[mf][h];
                v += __shfl_xor_sync(0xffffffffu, v, 1);
                v += __shfl_xor_sync(0xffffffffu, v, 2);
                p[mf][h] = v;
            }
        if (ctg == 0) {
            #pragma unroll
            for (int mf = 0; mf < 4; ++mf)
                #pragma unroll
                for (int h = 0; h < 2; ++h) {
                    int r = mf * 16 + gid + h * 8;
                    SP[wn * MT + r] = p[mf][h];
                }
        }
    }
    __syncthreads();
    if (tid < MT) {
        float s = 0.f;
        #pragma unroll
        for (int w = 0; w < 8; ++w) s += SP[w * MT + tid];
        SA[tid] = s;
    }
    __syncthreads();

    if (wid < 2) {     // one warp per batch row (MT=64 -> 2 rows)
        float v = SA[wid * LL + lane];
        float m = v;
        #pragma unroll
        for (int o = 16; o; o >>= 1) m = fmaxf(m, __shfl_xor_sync(0xffffffffu, m, o));
        float e = __expf(v - m);
        float sum = e;
        #pragma unroll
        for (int o = 16; o; o >>= 1) sum += __shfl_xor_sync(0xffffffffu, sum, o);
        SAL[wid * LL + lane] = e / sum;
    }
    __syncthreads();

    for (int idx = tid; idx < 2 * DD; idx += GT) {
        int bb = idx / DD, d = idx - bb * DD;
        float o = 0.f;
        #pragma unroll
        for (int l = 0; l < LL; ++l)
            o = fmaf(SAL[bb * LL + l], Xs[(bb * LL + l) * XS + d], o);
        out[(size_t)(blockIdx.x * 2 + bb) * DD + d] = o;
    }
}

extern "C" void kernel_launch(void* const* d_in, const int* in_sizes, int n_in,
                              void* d_out, int out_size) {
    const int*   title = (const int*)  d_in[0];
    const float* emb   = (const float*)d_in[1];
    const float* pos   = (const float*)d_in[2];
    const float* Wq    = (const float*)d_in[3];
    const float* bq    = (const float*)d_in[4];
    const float* Wk    = (const float*)d_in[5];
    const float* bk    = (const float*)d_in[6];
    const float* Wv    = (const float*)d_in[7];
    const float* bv    = (const float*)d_in[8];
    const float* Wo    = (const float*)d_in[9];
    const float* bo    = (const float*)d_in[10];
    const float* Va    = (const float*)d_in[11];
    const float* ba    = (const float*)d_in[12];
    const float* qw    = (const float*)d_in[13];
    float* out = (float*)d_out;

    size_t sh_gemm = (size_t)MT * XS * sizeof(float);                        // 82,944
    size_t sh_de   = sh_gemm + (size_t)(8 * MT + 2 * MT) * sizeof(float);    // 85,504
    size_t sh_attn = (size_t)3 * LL * AS * sizeof(float);

    cudaFuncSetAttribute(qkv_kernel, cudaFuncAttributeMaxDynamicSharedMemorySize, (int)sh_gemm);
    cudaFuncSetAttribute(de_kernel,  cudaFuncAttributeMaxDynamicSharedMemorySize, (int)sh_de);
    cudaFuncSetAttribute(attn_kernel,cudaFuncAttributeMaxDynamicSharedMemorySize, (int)sh_attn);

    dim3 pgrid(48, 5);
    prep_kernel<<<pgrid, 256>>>(Wq, Wk, Wv, Wo, Va);

    qkv_kernel<<<BB * LL / MT, GT, sh_gemm>>>(title, emb, pos, bq, bk, bv);

    attn_kernel<<<BB, 192, sh_attn>>>(nullptr);

    de_kernel<<<BB * LL / MT, GT, sh_de>>>(bo, ba, qw, out);
}

// round 8
// speedup vs baseline: 3.0289x; 1.7413x over previous
#include <cuda_runtime.h>
#include <math.h>

#define BB 4096
#define LL 32
#define DD 300
#define HH 6
#define HDD 50
#define NKC 38
#define XSS 308      // Xs / ctx2 stride (floats): conflict-free A-frag LDS
#define KVS 300      // K,V stride
#define MT 64        // rows per CTA = 2 batch rows
#define GT 256       // 8 warps, all across N; warp tile 64 x 40

// Fragment-packed weights: g_Wb[m][((kc*8 + wn)*5 + nc)*32 + lane] =
//   { W[wn*40+nc*8+gid][kc*8+ctg], W[...][kc*8+ctg+4] }  (zero-padded, tf32-rounded)
#define WB_PER_M (NKC * 8 * 5 * 32)
__device__ float2 g_Wb[5][WB_PER_M];

// smem float offsets
#define OFF_K   (MT * XSS)                  // 19712
#define OFF_V   (OFF_K + MT * KVS)          // 38912
#define OFF_CT  OFF_K                       // ctx2 reuses K/V region, stride XSS
#define OFF_SP  (OFF_CT + MT * XSS)         // 39424 (beyond ctx2 end)
#define OFF_SA  (OFF_SP + 8 * MT)
#define OFF_SAL (OFF_SA + MT)
#define SMEM_FLOATS (OFF_V + MT * KVS)      // 58112 -> 232448 bytes

__device__ __forceinline__ float tf32r(float x) {
    unsigned r;
    asm("cvt.rna.tf32.f32 %0, %1;" : "=r"(r) : "f"(x));
    return __uint_as_float(r);
}

__device__ __forceinline__ float tanh_fast(float x) {
    float y;
    asm("tanh.approx.f32 %0, %1;" : "=f"(y) : "f"(x));
    return y;
}

__device__ __forceinline__ void mma8(float c[4], const float a[4], float b0, float b1) {
    asm volatile(
        "mma.sync.aligned.m16n8k8.row.col.f32.tf32.tf32.f32 "
        "{%0,%1,%2,%3},{%4,%5,%6,%7},{%8,%9},{%0,%1,%2,%3};"
        : "+f"(c[0]), "+f"(c[1]), "+f"(c[2]), "+f"(c[3])
        : "r"(__float_as_uint(a[0])), "r"(__float_as_uint(a[1])),
          "r"(__float_as_uint(a[2])), "r"(__float_as_uint(a[3])),
          "r"(__float_as_uint(b0)), "r"(__float_as_uint(b1)));
}

__global__ void prep_kernel(const float* __restrict__ Wq, const float* __restrict__ Wk,
                            const float* __restrict__ Wv, const float* __restrict__ Wo,
                            const float* __restrict__ Va) {
    const float* src;
    int m = blockIdx.y;
    switch (m) {
        case 0: src = Wq; break;
        case 1: src = Wk; break;
        case 2: src = Wv; break;
        case 3: src = Wo; break;
        default: src = Va; break;
    }
    float2* dst = g_Wb[m];
    for (int idx = blockIdx.x * blockDim.x + threadIdx.x; idx < WB_PER_M;
         idx += gridDim.x * blockDim.x) {
        int lane = idx & 31;
        int t1   = idx >> 5;
        int nc   = t1 % 5;
        int t2   = t1 / 5;
        int wn   = t2 & 7;
        int kc   = t2 >> 3;
        int gid = lane >> 2, ctg = lane & 3;
        int n = wn * 40 + nc * 8 + gid;
        int k = kc * 8 + ctg;
        float2 f = make_float2(0.f, 0.f);
        if (n < DD) {
            if (k < DD)     f.x = tf32r(src[n * DD + k]);
            if (k + 4 < DD) f.y = tf32r(src[n * DD + k + 4]);
        }
        dst[idx] = f;
    }
}

// GEMM mainloop: A = S[64][XSS] (smem), B = packed fragments (register double-buffered)
__device__ __forceinline__ void gemm_main(const float* __restrict__ S,
                                          const float2* __restrict__ wb0,
                                          int gid, int ctg, float c[4][5][4]) {
    #pragma unroll
    for (int mf = 0; mf < 4; ++mf)
        #pragma unroll
        for (int nc = 0; nc < 5; ++nc)
            #pragma unroll
            for (int i = 0; i < 4; ++i) c[mf][nc][i] = 0.f;

    float2 bcur[5];
    #pragma unroll
    for (int nc = 0; nc < 5; ++nc) bcur[nc] = wb0[nc * 32];

    #pragma unroll 2
    for (int kc = 0; kc < NKC; ++kc) {
        float2 bnxt[5];
        if (kc + 1 < NKC) {
            const float2* w2 = wb0 + (size_t)(kc + 1) * (8 * 5 * 32);
            #pragma unroll
            for (int nc = 0; nc < 5; ++nc) bnxt[nc] = w2[nc * 32];
        }
        const int k0 = kc * 8;
        float a[4][4];
        #pragma unroll
        for (int mf = 0; mf < 4; ++mf) {
            const float* xr = S + (mf * 16 + gid) * XSS + k0;
            a[mf][0] = xr[ctg];
            a[mf][1] = xr[8 * XSS + ctg];
            a[mf][2] = xr[ctg + 4];
            a[mf][3] = xr[8 * XSS + ctg + 4];
        }
        #pragma unroll
        for (int nc = 0; nc < 5; ++nc)
            #pragma unroll
            for (int mf = 0; mf < 4; ++mf)
                mma8(c[mf][nc], a[mf], bcur[nc].x, bcur[nc].y);
        #pragma unroll
        for (int nc = 0; nc < 5; ++nc) bcur[nc] = bnxt[nc];
    }
}

__global__ __launch_bounds__(GT, 1)
void fused_kernel(const int* __restrict__ title,
                  const float* __restrict__ emb,
                  const float* __restrict__ pos,
                  const float* __restrict__ bq,
                  const float* __restrict__ bk,
                  const float* __restrict__ bv,
                  const float* __restrict__ bo,
                  const float* __restrict__ ba,
                  const float* __restrict__ qw,
                  float* __restrict__ out) {
    extern __shared__ float sm[];
    float* Xs = sm;                 // [64][308]  x -> Q -> ctx
    float* SK = sm + OFF_K;         // [64][300]
    float* SV = sm + OFF_V;         // [64][300]
    float* CT = sm + OFF_CT;        // [64][308]  ctx2 (reuses K/V region)
    float* SP = sm + OFF_SP;
    float* SA = sm + OFF_SA;
    float* SAL = sm + OFF_SAL;

    const int tid = threadIdx.x;
    const int lane = tid & 31, wid = tid >> 5;
    const int gid = lane >> 2, ctg = lane & 3;
    const int wn = wid;
    const int r0 = blockIdx.x * MT;

    // tokens live in Xs pad cols [304..307] (no static smem)
    if (tid < MT) ((int*)Xs)[tid * XSS + 304] = title[r0 + tid];
    __syncthreads();

    // ---- gather x = tf32(emb[tok] + pos); cols 300..303 zeroed ----
    for (int idx = tid; idx < MT * 76; idx += GT) {
        int r = idx / 76, j = idx - r * 76;
        float4 v = make_float4(0.f, 0.f, 0.f, 0.f);
        if (j < 75) {
            int tok = ((const int*)Xs)[r * XSS + 304];
            float4 e = *(const float4*)&emb[(size_t)tok * DD + 4 * j];
            float4 p = *(const float4*)&pos[(r & (LL - 1)) * DD + 4 * j];
            v.x = tf32r(e.x + p.x); v.y = tf32r(e.y + p.y);
            v.z = tf32r(e.z + p.z); v.w = tf32r(e.w + p.w);
        }
        *(float4*)&Xs[r * XSS + 4 * j] = v;
    }
    __syncthreads();

    float c[4][5][4];

    // ---- K = x @ Wk^T + bk -> SK ----
    gemm_main(Xs, g_Wb[1] + (size_t)wn * 5 * 32 + lane, gid, ctg, c);
    #pragma unroll
    for (int mf = 0; mf < 4; ++mf)
        #pragma unroll
        for (int nc = 0; nc < 5; ++nc) {
            int n = wn * 40 + nc * 8 + 2 * ctg;
            if (n < DD) {
                float b0 = bk[n], b1 = bk[n + 1];
                #pragma unroll
                for (int h = 0; h < 2; ++h) {
                    int r = mf * 16 + gid + h * 8;
                    SK[r * KVS + n]     = c[mf][nc][2 * h]     + b0;
                    SK[r * KVS + n + 1] = c[mf][nc][2 * h + 1] + b1;
                }
            }
        }

    // ---- V = x @ Wv^T + bv -> SV ----
    gemm_main(Xs, g_Wb[2] + (size_t)wn * 5 * 32 + lane, gid, ctg, c);
    #pragma unroll
    for (int mf = 0; mf < 4; ++mf)
        #pragma unroll
        for (int nc = 0; nc < 5; ++nc) {
            int n = wn * 40 + nc * 8 + 2 * ctg;
            if (n < DD) {
                float b0 = bv[n], b1 = bv[n + 1];
                #pragma unroll
                for (int h = 0; h < 2; ++h) {
                    int r = mf * 16 + gid + h * 8;
                    SV[r * KVS + n]     = c[mf][nc][2 * h]     + b0;
                    SV[r * KVS + n + 1] = c[mf][nc][2 * h + 1] + b1;
                }
            }
        }

    // ---- Q = (x @ Wq^T + bq)/sqrt(HD) -> Xs (after all warps done reading x) ----
    gemm_main(Xs, g_Wb[0] + (size_t)wn * 5 * 32 + lane, gid, ctg, c);
    const float rs = rsqrtf((float)HDD);
    __syncthreads();
    #pragma unroll
    for (int mf = 0; mf < 4; ++mf)
        #pragma unroll
        for (int nc = 0; nc < 5; ++nc) {
            int n = wn * 40 + nc * 8 + 2 * ctg;
            if (n < DD) {
                float b0 = bq[n], b1 = bq[n + 1];
                #pragma unroll
                for (int h = 0; h < 2; ++h) {
                    int r = mf * 16 + gid + h * 8;
                    Xs[r * XSS + n]     = (c[mf][nc][2 * h]     + b0) * rs;
                    Xs[r * XSS + n + 1] = (c[mf][nc][2 * h + 1] + b1) * rs;
                }
            }
        }
    __syncthreads();

    // ---- attention: 12 (brow,head) pairs over 8 warps; ctx -> Xs (tf32r) ----
    for (int p = wid; p < 2 * HH; p += 8) {
        int br = p / HH, h = p - HH * (p / HH);
        int off = h * HDD;
        const float* Qb = Xs + (br * LL) * XSS;
        const float* Kb = SK + (br * LL) * KVS;
        const float* Vb = SV + (br * LL) * KVS;
        const int i = lane;
        float s[LL];
        #pragma unroll
        for (int j = 0; j < LL; ++j) s[j] = 0.f;
        for (int hd2 = 0; hd2 < HDD / 2; ++hd2) {
            float2 q2 = *(const float2*)&Qb[i * XSS + off + 2 * hd2];
            #pragma unroll
            for (int j = 0; j < LL; ++j) {
                float2 k2 = *(const float2*)&Kb[j * KVS + off + 2 * hd2];
                s[j] = fmaf(q2.x, k2.x, fmaf(q2.y, k2.y, s[j]));
            }
        }
        float m = -1e30f;
        #pragma unroll
        for (int j = 0; j < LL; ++j) m = fmaxf(m, s[j]);
        float sum = 0.f;
        #pragma unroll
        for (int j = 0; j < LL; ++j) { s[j] = __expf(s[j] - m); sum += s[j]; }
        float inv = 1.f / sum;
        #pragma unroll
        for (int j = 0; j < LL; ++j) s[j] *= inv;
        for (int hd2 = 0; hd2 < HDD / 2; ++hd2) {
            float cx = 0.f, cy = 0.f;
            #pragma unroll
            for (int j = 0; j < LL; ++j) {
                float2 v2 = *(const float2*)&Vb[j * KVS + off + 2 * hd2];
                cx = fmaf(s[j], v2.x, cx);
                cy = fmaf(s[j], v2.y, cy);
            }
            float2 o2 = make_float2(tf32r(cx), tf32r(cy));
            *(float2*)&Xs[(br * LL + i) * XSS + off + 2 * hd2] = o2;
        }
    }
    __syncthreads();

    // ---- ctx2 = ctx @ Wo^T + bo -> CT (reuses K/V region; pads zeroed) ----
    gemm_main(Xs, g_Wb[3] + (size_t)wn * 5 * 32 + lane, gid, ctg, c);
    #pragma unroll
    for (int mf = 0; mf < 4; ++mf)
        #pragma unroll
        for (int nc = 0; nc < 5; ++nc) {
            int n = wn * 40 + nc * 8 + 2 * ctg;
            if (n < DD) {
                float b0 = bo[n], b1 = bo[n + 1];
                #pragma unroll
                for (int h = 0; h < 2; ++h) {
                    int r = mf * 16 + gid + h * 8;
                    CT[r * XSS + n]     = c[mf][nc][2 * h]     + b0;
                    CT[r * XSS + n + 1] = c[mf][nc][2 * h + 1] + b1;
                }
            }
        }
    CT[(tid >> 2) * XSS + 300 + (tid & 3)] = 0.f;   // zero pad cols 300..303
    __syncthreads();

    // ---- scores: a[l] = sum_n tanh(ctx2 @ Va^T + ba)[l][n] * qw[n] ----
    gemm_main(CT, g_Wb[4] + (size_t)wn * 5 * 32 + lane, gid, ctg, c);
    {
        float p[4][2];
        #pragma unroll
        for (int mf = 0; mf < 4; ++mf) { p[mf][0] = 0.f; p[mf][1] = 0.f; }
        #pragma unroll
        for (int mf = 0; mf < 4; ++mf)
            #pragma unroll
            for (int nc = 0; nc < 5; ++nc)
                #pragma unroll
                for (int i = 0; i < 4; ++i) {
                    int n = wn * 40 + nc * 8 + 2 * ctg + (i & 1);
                    if (n < DD) {
                        float tv = tanh_fast(c[mf][nc][i] + ba[n]);
                        p[mf][i >> 1] = fmaf(tv, qw[n], p[mf][i >> 1]);
                    }
                }
        #pragma unroll
        for (int mf = 0; mf < 4; ++mf)
            #pragma unroll
            for (int h = 0; h < 2; ++h) {
                float v = p[mf][h];
                v += __shfl_xor_sync(0xffffffffu, v, 1);
                v += __shfl_xor_sync(0xffffffffu, v, 2);
                p[mf][h] = v;
            }
        if (ctg == 0) {
            #pragma unroll
            for (int mf = 0; mf < 4; ++mf)
                #pragma unroll
                for (int h = 0; h < 2; ++h) {
                    int r = mf * 16 + gid + h * 8;
                    SP[wn * MT + r] = p[mf][h];
                }
        }
    }
    __syncthreads();
    if (tid < MT) {
        float s = 0.f;
        #pragma unroll
        for (int w = 0; w < 8; ++w) s += SP[w * MT + tid];
        SA[tid] = s;
    }
    __syncthreads();

    if (wid < 2) {      // one warp per batch row
        float v = SA[wid * LL + lane];
        float m = v;
        #pragma unroll
        for (int o = 16; o; o >>= 1) m = fmaxf(m, __shfl_xor_sync(0xffffffffu, m, o));
        float e = __expf(v - m);
        float sum = e;
        #pragma unroll
        for (int o = 16; o; o >>= 1) sum += __shfl_xor_sync(0xffffffffu, sum, o);
        SAL[wid * LL + lane] = e / sum;
    }
    __syncthreads();

    for (int idx = tid; idx < 2 * DD; idx += GT) {
        int bb = idx / DD, d = idx - bb * DD;
        float o = 0.f;
        #pragma unroll
        for (int l = 0; l < LL; ++l)
            o = fmaf(SAL[bb * LL + l], CT[(bb * LL + l) * XSS + d], o);
        out[(size_t)(blockIdx.x * 2 + bb) * DD + d] = o;
    }
}

extern "C" void kernel_launch(void* const* d_in, const int* in_sizes, int n_in,
                              void* d_out, int out_size) {
    const int*   title = (const int*)  d_in[0];
    const float* emb   = (const float*)d_in[1];
    const float* pos   = (const float*)d_in[2];
    const float* Wq    = (const float*)d_in[3];
    const float* bq    = (const float*)d_in[4];
    const float* Wk    = (const float*)d_in[5];
    const float* bk    = (const float*)d_in[6];
    const float* Wv    = (const float*)d_in[7];
    const float* bv    = (const float*)d_in[8];
    const float* Wo    = (const float*)d_in[9];
    const float* bo    = (const float*)d_in[10];
    const float* Va    = (const float*)d_in[11];
    const float* ba    = (const float*)d_in[12];
    const float* qw    = (const float*)d_in[13];
    float* out = (float*)d_out;

    size_t shbytes = (size_t)SMEM_FLOATS * sizeof(float);   // 232448 = 227 KB opt-in max
    cudaFuncSetAttribute(fused_kernel,
                         cudaFuncAttributeMaxDynamicSharedMemorySize, (int)shbytes);

    dim3 pgrid(48, 5);
    prep_kernel<<<pgrid, 256>>>(Wq, Wk, Wv, Wo, Va);

    fused_kernel<<<BB * LL / MT, GT, shbytes>>>(title, emb, pos,
                                                bq, bk, bv, bo, ba, qw, out);
}